// round 17
// baseline (speedup 1.0000x reference)
#include <cuda_runtime.h>

#define NB 16
#define NC 64
#define HW 65536
#define NBINS 256
#define NA   128              // stage A blocks: 2 per plane
#define NCOS 256              // BC blocks: 256 px each, smem-resident
#define NBLK (NA + NCOS)      // 384; 3 blocks/SM x 148 = 444 capacity
#define SMEM_BYTES (69 * 1024)

// ---- scratch (no allocations allowed) ----
__device__ float         d_part[NB * NC * 2];   // per-(plane,half) partial sums
__device__ unsigned int  d_hist[NB * NBINS];
__device__ float         d_scale[NB * NBINS];
__device__ unsigned int  d_cA[NB];              // A arrivals   (==NA: sums ready)
__device__ unsigned int  d_cH[NB];              // BC arrivals  (==NCOS+1: LUT ready)
__device__ unsigned int  d_cM[NB];              // BC write-done (==NCOS)

__global__ void k_init() {
    d_hist[blockIdx.x * NBINS + threadIdx.x] = 0u;
    if (threadIdx.x == 0) {
        d_cA[blockIdx.x] = 0u; d_cH[blockIdx.x] = 0u; d_cM[blockIdx.x] = 0u;
    }
}

__device__ __forceinline__ void spin_ge(const unsigned int* p, unsigned int v) {
    const volatile unsigned int* vp = (const volatile unsigned int*)p;
    while (*vp < v) { }
}

// ============================================================
// Two-stage persistent pipeline:
//   A (128): plane-mean partials for slot b (DRAM -> L2 fill), 3 slots ahead max
//   BC(256): load 256px x 64ch to SMEM, cos/q/hist, LUT rendezvous,
//            multiply FROM SMEM, write out.  F read once per slot.
// ============================================================
__global__ void __launch_bounds__(256, 3) k_pipe(const float* __restrict__ F,
                                                 float* __restrict__ out) {
    extern __shared__ char smem[];
    float*        sF   = (float*)smem;                   // 64 KB: 64ch x 256px
    float*        sRed = (float*)(smem + 65536);         // 1 KB reduce / cdf
    float*        sAh  = sRed + 256;                     // 1 KB a-hat / scan tmp
    unsigned int* sU   = (unsigned int*)(sAh + 256);     // 1 KB block hist
    int*          sLast = (int*)(sU + 256);

    const int tid = threadIdx.x;
    const int bid = blockIdx.x;

    if (bid < NA) {
        // ================= Stage A: plane-mean partials ==================
        const int c = bid >> 1, half = bid & 1;
        for (int b = 0; b < NB; ++b) {
            if (b >= 3) {                        // <=3 live slabs (48 MB) in L2
                if (tid == 0) spin_ge(&d_cM[b - 3], NCOS);
                __syncthreads();
            }
            const float4* base = (const float4*)F +
                ((size_t)(b * NC + c) << 14) + ((size_t)half << 13);
            float s = 0.f;
            #pragma unroll 8
            for (int j = 0; j < 32; ++j) {       // 8192 float4 / 256 thr
                float4 v = __ldcg(base + j * 256 + tid);   // fill L2, skip L1
                s += (v.x + v.y) + (v.z + v.w);
            }
            sRed[tid] = s;
            __syncthreads();
            for (int o = 128; o > 0; o >>= 1) {
                if (tid < o) sRed[tid] += sRed[tid + o];
                __syncthreads();
            }
            if (tid == 0) {
                d_part[(b * NC + c) * 2 + half] = sRed[0];
                __threadfence();
                atomicAdd(&d_cA[b], 1u);
            }
            __syncthreads();
        }
    } else {
        // ================= Stage BC: everything else ==================
        const int sub = bid - NA;                // 0..255
        const int px  = (sub << 8) + tid;        // this thread's pixel (scalar)

        for (int b = 0; b < NB; ++b) {
            if (tid == 0) spin_ge(&d_cA[b], NA); // A finished >=1 slot ago
            __syncthreads();
            __threadfence();

            // ---- a-hat (fixed-order combine of the two halves) ----
            sU[tid] = 0u;
            if (tid < NC)
                sAh[tid] = (d_part[(b * NC + tid) * 2] +
                            d_part[(b * NC + tid) * 2 + 1]) * (1.0f / HW);
            __syncthreads();
            sRed[tid] = (tid < NC) ? sAh[tid] * sAh[tid] : 0.f;
            __syncthreads();
            for (int o = 128; o > 0; o >>= 1) {
                if (tid < o) sRed[tid] += sRed[tid + o];
                __syncthreads();
            }
            const float inv = 1.0f / fmaxf(sqrtf(sRed[0]), 1e-12f);
            __syncthreads();
            if (tid < NC) sAh[tid] *= inv;
            __syncthreads();

            // ---- load 64 channels of my pixel into SMEM, accumulate cos ----
            // NOTE: scalar indexing -> batch slab is NC*HW = 2^22 floats
            const float* Fb = F + ((size_t)b << 22) + px;
            float dot = 0.f, ss = 0.f;
            #pragma unroll 8
            for (int c = 0; c < NC; ++c) {
                float v = __ldcg(Fb + ((size_t)c << 16));  // L2-hot (A filled)
                sF[c * 256 + tid] = v;
                dot += sAh[c] * v;
                ss  += v * v;
            }
            const int q = ((int)((dot / fmaxf(sqrtf(ss), 1e-12f)) * 255.0f)) & 255;

            atomicAdd(&sU[q], 1u);
            __syncthreads();
            unsigned int cnt = sU[tid];
            if (cnt) atomicAdd(&d_hist[b * NBINS + tid], cnt);
            __syncthreads();

            if (tid == 0) {
                __threadfence();
                sLast[0] = (atomicAdd(&d_cH[b], 1u) == NCOS - 1);
            }
            __syncthreads();

            if (sLast[0]) {                      // last BC block: build LUT
                __threadfence();
                float h = (float)d_hist[b * NBINS + tid];
                float* cdf = sRed;
                float* tmp = sAh;                // a-hat no longer needed
                cdf[tid] = h;
                __syncthreads();
                for (int o = 1; o < NBINS; o <<= 1) {
                    float v = cdf[tid];
                    float add = (tid >= o) ? cdf[tid - o] : 0.f;
                    __syncthreads();
                    cdf[tid] = v + add;
                    __syncthreads();
                }
                tmp[tid] = (h > 0.f) ? cdf[tid] : (float)(HW + 1);
                __syncthreads();
                for (int o = 128; o > 0; o >>= 1) {
                    if (tid < o) tmp[tid] = fminf(tmp[tid], tmp[tid + o]);
                    __syncthreads();
                }
                float cmin  = tmp[0];
                float denom = fmaxf((float)HW - cmin, 1.0f);
                float lut   = rintf((cdf[tid] - cmin) * (255.0f / denom));
                lut = fminf(fmaxf(lut, 0.0f), 255.0f);
                d_scale[b * NBINS + tid] = lut * (1.0f / 255.0f);
                __syncthreads();
                if (tid == 0) {
                    __threadfence();
                    atomicAdd(&d_cH[b], 1u);     // -> NCOS+1 : LUT ready
                }
            }

            // ---- wait LUT, then multiply FROM SMEM and stream out ----
            if (tid == 0) spin_ge(&d_cH[b], NCOS + 1);
            __syncthreads();
            __threadfence();

            const float s = __ldg(d_scale + b * NBINS + q);   // 1 lookup/thread
            float* Ob = out + ((size_t)b << 22) + px;         // scalar: 2^22/batch
            #pragma unroll 8
            for (int c = 0; c < NC; ++c) {
                float v = sF[c * 256 + tid];
                Ob[(size_t)c << 16] = v * s;     // coalesced 128B/warp stores
            }
            if (tid == 0) {
                __threadfence();
                atomicAdd(&d_cM[b], 1u);
            }
            __syncthreads();                     // sF reused next slot
        }
    }
}

// ============================================================
extern "C" void kernel_launch(void* const* d_in, const int* in_sizes, int n_in,
                              void* d_out, int out_size) {
    const float* F = (const float*)d_in[0];
    float* out = (float*)d_out;
    (void)in_sizes; (void)n_in; (void)out_size;

    cudaFuncSetAttribute(k_pipe, cudaFuncAttributeMaxDynamicSharedMemorySize,
                         SMEM_BYTES);
    k_init<<<NB, NBINS>>>();
    k_pipe<<<NBLK, 256, SMEM_BYTES>>>(F, out);
}